// round 13
// baseline (speedup 1.0000x reference)
#include <cuda_runtime.h>
#include <cuda_fp16.h>
#include <mma.h>
#include <cstdint>

using namespace nvcuda;

#define NN 100000
#define NNP 100096          // 782 * 128, padded for TC GEMM tiles
#define NE 3200000
#define HID 128
#define OUTF 64
#define SCAN_NB 391         // ceil(NN/256)
#define EBF 6250            // NE/(256*2) edge blocks, 2 edges/thread
#define WB 12500            // warp-per-node blocks

// ---------------- device scratch (static, no allocation) ----------------
// Symbols referenced ONLY inside device code (never passed from host).
__device__ int    g_degout[NN];
__device__ int    g_degin[NN];
__device__ float  g_stats[512];
__device__ unsigned long long g_scanstate[SCAN_NB];

__device__ int    g_is64;
__device__ float  g_norms[NN];
__device__ float  g_normd[NN];
__device__ float  g_sumns[NN];                // written by spgemm<0> phase 1
__device__ int    g_rowptr[NN + 1];
__device__ int    g_srci[NE];
__device__ unsigned g_dstr[NE];               // dst | (rank << 17)
__device__ int    g_col[NE];
__device__ __half g_gat16[(size_t)NNP * HID]; // x*ns -> (L1 out) v2 ; pad rows 0
__device__ __half g_agg16[(size_t)NNP * HID]; // (L0 out) v1        ; pad rows 0
__device__ __half g_z16[(size_t)NN * OUTF];
__device__ __half g_w1[HID * HID];
__device__ __half g_w2[HID * HID];
__device__ __half g_w3p[HID * OUTF];          // sc2 ⊙ W3
__device__ float  g_c3[OUTF];                 // sh2 @ W3
__device__ float  g_scale1[HID], g_shift1[HID];

// ---------------- init: zero accumulators + detect dtype + convert W1/W2 ----
__global__ void init_kernel(const void* src, const float* __restrict__ W1,
                            const float* __restrict__ W2) {
    int i = blockIdx.x * blockDim.x + threadIdx.x;   // 391*256 = 100096
    if (i < NN) { g_degout[i] = 0; g_degin[i] = 0; }
    if (i < 512) g_stats[i] = 0.f;
    if (i < SCAN_NB) g_scanstate[i] = 0ull;
    if (i < HID * HID) {
        g_w1[i] = __float2half_rn(W1[i]);
        g_w2[i] = __float2half_rn(W2[i]);
    }
    if (i == 0) {
        const long long* p = (const long long*)src;
        int ok = 1;
        #pragma unroll 1
        for (int k = 0; k < 128; k++) {
            long long v = p[k];
            if (v < 0 || v >= NN) { ok = 0; break; }
        }
        g_is64 = ok;
    }
}

// ---------------- degrees + int32 conversion + packed dst|rank --------------
__global__ void __launch_bounds__(256) degree_kernel(const void* src, const void* dst) {
    int p = blockIdx.x * blockDim.x + threadIdx.x;   // pair index
    int e = p * 2;
    if (e >= NE) return;
    int s0, s1, d0, d1;
    if (g_is64) {
        longlong2 a = ((const longlong2*)src)[p];
        longlong2 b = ((const longlong2*)dst)[p];
        s0 = (int)a.x; s1 = (int)a.y;
        d0 = (int)b.x; d1 = (int)b.y;
    } else {
        int2 a = ((const int2*)src)[p];
        int2 b = ((const int2*)dst)[p];
        s0 = a.x; s1 = a.y;
        d0 = b.x; d1 = b.y;
    }
    *(int2*)(g_srci + e) = make_int2(s0, s1);
    atomicAdd(&g_degout[s0], 1);
    atomicAdd(&g_degout[s1], 1);
    unsigned r0 = (unsigned)atomicAdd(&g_degin[d0], 1);
    unsigned r1 = (unsigned)atomicAdd(&g_degin[d1], 1);
    *(uint2*)(g_dstr + e) = make_uint2((unsigned)d0 | (r0 << 17),
                                       (unsigned)d1 | (r1 << 17));
}

// ---------------- single-pass scan (decoupled lookback) + norms -------------
__global__ void __launch_bounds__(256) scan_kernel() {
    int bid = blockIdx.x;
    int t = threadIdx.x;
    int lane = t & 31, wid = t >> 5;
    int i = bid * 256 + t;
    int v = (i < NN) ? g_degin[i] : 0;

    int x = v;
    #pragma unroll
    for (int off = 1; off < 32; off <<= 1) {
        int y = __shfl_up_sync(0xffffffffu, x, off);
        if (lane >= off) x += y;
    }
    __shared__ int wsum[8];
    if (lane == 31) wsum[wid] = x;
    __syncthreads();
    if (wid == 0 && lane < 8) {
        int w = wsum[lane];
        #pragma unroll
        for (int off = 1; off < 8; off <<= 1) {
            int y = __shfl_up_sync(0xffu, w, off);
            if (lane >= off) w += y;
        }
        wsum[lane] = w;
    }
    __syncthreads();
    int incl = x + (wid > 0 ? wsum[wid - 1] : 0);
    int bsum = wsum[7];

    __shared__ int s_excl;
    if (t == 0) {
        if (bid == 0) {
            atomicExch(&g_scanstate[0], (2ull << 32) | (unsigned long long)(unsigned)bsum);
            s_excl = 0;
        } else {
            atomicExch(&g_scanstate[bid], (1ull << 32) | (unsigned long long)(unsigned)bsum);
            long long running = 0;
            int j = bid - 1;
            while (true) {
                unsigned long long st = atomicAdd(&g_scanstate[j], 0ull);
                unsigned f = (unsigned)(st >> 32);
                if (f == 0u) continue;
                running += (long long)(unsigned)st;
                if (f == 2u) break;
                j--;
            }
            s_excl = (int)running;
            atomicExch(&g_scanstate[bid],
                       (2ull << 32) | (unsigned long long)(unsigned)(running + bsum));
        }
    }
    __syncthreads();
    int base = s_excl;
    if (i < NN) {
        int r = base + incl - v;
        g_rowptr[i] = r;
        int dout = g_degout[i]; if (dout < 1) dout = 1;
        int din = v; if (din < 1) din = 1;
        g_norms[i] = rsqrtf((float)dout);
        g_normd[i] = rsqrtf((float)din);
        if (i == NN - 1) g_rowptr[NN] = r + v;
    }
}

// ---------------- fused: atomic-free CSR fill (rank trick) + prepx ----------
__global__ void __launch_bounds__(256) fillprep_kernel(const float* __restrict__ x) {
    int b = blockIdx.x;
    if (b < EBF) {
        int p = b * 256 + threadIdx.x;
        int e = p * 2;
        int2 ss = *(const int2*)(g_srci + e);
        uint2 dr = *(const uint2*)(g_dstr + e);
        g_col[g_rowptr[dr.x & 0x1FFFF] + (dr.x >> 17)] = ss.x;
        g_col[g_rowptr[dr.y & 0x1FFFF] + (dr.y >> 17)] = ss.y;
    } else {
        int t = (b - EBF) * 256 + threadIdx.x;
        int node = t >> 5;
        if (node >= NN) return;
        int c = (t & 31) * 4;
        float ns = g_norms[node];
        float4 v = *(const float4*)(x + (size_t)node * HID + c);
        __half2 h0 = __floats2half2_rn(v.x * ns, v.y * ns);
        __half2 h1 = __floats2half2_rn(v.z * ns, v.w * ns);
        uint2 u;
        u.x = *(unsigned*)&h0;
        u.y = *(unsigned*)&h1;
        *(uint2*)(g_gat16 + (size_t)node * HID + c) = u;
    }
}

// ---------------- fused SpMM + TC GEMM per layer -----------------------------
// L=0: gather from g_gat16 (x*ns), GEMM W1, epilogue v1=relu(.+b1)*ns -> g_agg16;
//      stats@0; also writes sumns (broadcast norms loads in phase 1).
// L=1: gather from g_agg16 (v1), affine1 via sumns, GEMM W2,
//      epilogue v2=relu(.+b2)*ns -> g_gat16; stats@256.
// Block = 128 dst nodes, 8 warps; phase 1: warp-per-node spmm into smem tile;
// phase 2: wmma off the smem tile (B fragments from global, L1-hot).
template<int L>
__global__ void __launch_bounds__(256) spgemm_kernel(const float* __restrict__ bias) {
    constexpr bool AFFINE = (L == 1);
    const __half* __restrict__ G = AFFINE ? g_agg16 : g_gat16;   // gather source
    __half* __restrict__ C = AFFINE ? g_gat16 : g_agg16;         // epilogue out
    const __half* __restrict__ W = AFFINE ? g_w2 : g_w1;
    const int stats_off = AFFINE ? 256 : 0;

    __shared__ __align__(32) unsigned char sraw[128 * 128 * 2]; // 32KB: sAgg then sC
    __shared__ float sstat[2][4][64];
    __half* sAgg = (__half*)sraw;
    float* sC = (float*)sraw;

    int tid = threadIdx.x;
    int w = tid >> 5;
    int lane = tid & 31;
    int row0 = blockIdx.x * 128;
    int c = lane * 4;
    const __half* __restrict__ gbase = G + c;

    // ---- phase 1: SpMM, warp processes its 16 rows ----
    for (int lr = w * 16; lr < w * 16 + 16; lr++) {
        int d = row0 + lr;
        uint2 o = make_uint2(0u, 0u);
        if (d < NN) {
            int beg = g_rowptr[d], end = g_rowptr[d + 1];
            float ax = 0.f, ay = 0.f, az = 0.f, aw = 0.f;
            float ws = 0.f;
            int j = beg;
            for (; j + 3 < end; j += 4) {
                int s0 = g_col[j], s1 = g_col[j + 1], s2 = g_col[j + 2], s3 = g_col[j + 3];
                uint2 u0 = *(const uint2*)(gbase + (size_t)s0 * HID);
                uint2 u1 = *(const uint2*)(gbase + (size_t)s1 * HID);
                uint2 u2 = *(const uint2*)(gbase + (size_t)s2 * HID);
                uint2 u3 = *(const uint2*)(gbase + (size_t)s3 * HID);
                if (!AFFINE)
                    ws += (g_norms[s0] + g_norms[s1]) + (g_norms[s2] + g_norms[s3]);
                __half2 p0 = __hadd2(*(__half2*)&u0.x, *(__half2*)&u1.x);
                __half2 q0 = __hadd2(*(__half2*)&u2.x, *(__half2*)&u3.x);
                __half2 p1 = __hadd2(*(__half2*)&u0.y, *(__half2*)&u1.y);
                __half2 q1 = __hadd2(*(__half2*)&u2.y, *(__half2*)&u3.y);
                float2 f;
                f = __half22float2(p0); ax += f.x; ay += f.y;
                f = __half22float2(q0); ax += f.x; ay += f.y;
                f = __half22float2(p1); az += f.x; aw += f.y;
                f = __half22float2(q1); az += f.x; aw += f.y;
            }
            for (; j < end; j++) {
                int s = g_col[j];
                uint2 u = *(const uint2*)(gbase + (size_t)s * HID);
                if (!AFFINE) ws += g_norms[s];
                float2 a = __half22float2(*(__half2*)&u.x), b = __half22float2(*(__half2*)&u.y);
                ax += a.x; ay += a.y; az += b.x; aw += b.y;
            }
            float nd = g_normd[d];
            if (AFFINE) {
                float4 sc = *(const float4*)(g_scale1 + c);
                float4 sh = *(const float4*)(g_shift1 + c);
                float sn = g_sumns[d];
                ax = fmaf(sh.x, sn, ax * sc.x);
                ay = fmaf(sh.y, sn, ay * sc.y);
                az = fmaf(sh.z, sn, az * sc.z);
                aw = fmaf(sh.w, sn, aw * sc.w);
            } else {
                if (lane == 0) g_sumns[d] = ws;
            }
            __half2 h0 = __floats2half2_rn(ax * nd, ay * nd);
            __half2 h1 = __floats2half2_rn(az * nd, aw * nd);
            o.x = *(unsigned*)&h0;
            o.y = *(unsigned*)&h1;
        }
        *(uint2*)(sAgg + lr * HID + c) = o;
    }
    __syncthreads();

    // ---- phase 2: wmma GEMM, A from smem tile, B from global (L1-hot) ----
    wmma::fragment<wmma::accumulator, 16, 16, 16, float> acc[8];
    #pragma unroll
    for (int n = 0; n < 8; n++) wmma::fill_fragment(acc[n], 0.f);

    #pragma unroll
    for (int k = 0; k < 8; k++) {
        wmma::fragment<wmma::matrix_a, 16, 16, 16, __half, wmma::row_major> af;
        wmma::load_matrix_sync(af, sAgg + (w * 16) * HID + k * 16, HID);
        #pragma unroll
        for (int n = 0; n < 8; n++) {
            wmma::fragment<wmma::matrix_b, 16, 16, 16, __half, wmma::row_major> bf;
            wmma::load_matrix_sync(bf, W + (size_t)k * 16 * HID + n * 16, HID);
            wmma::mma_sync(acc[n], af, bf, acc[n]);
        }
    }
    __syncthreads();   // sAgg consumed; sC overlays it

    #pragma unroll
    for (int half = 0; half < 2; half++) {
        #pragma unroll
        for (int n = 0; n < 4; n++)
            wmma::store_matrix_sync(sC + w * 16 * 64 + n * 16, acc[half * 4 + n],
                                    64, wmma::mem_row_major);
        __syncthreads();

        int col = tid & 63;
        int q = tid >> 6;
        int gcol = half * 64 + col;
        float bb = bias[gcol];
        float ps = 0.f, pq = 0.f;
        #pragma unroll 4
        for (int r = q * 32; r < q * 32 + 32; r++) {
            int grow = row0 + r;
            if (grow < NN) {
                float v = sC[r * 64 + col] + bb;
                v = fmaxf(v, 0.f);
                ps += v;
                pq += v * v;
                v *= g_norms[grow];   // fold norm_s into stored operand
                C[(size_t)grow * HID + gcol] = __float2half_rn(v);
            }
        }
        sstat[0][q][col] = ps;
        sstat[1][q][col] = pq;
        __syncthreads();
        if (tid < 64) {
            float s = sstat[0][0][tid] + sstat[0][1][tid]
                    + sstat[0][2][tid] + sstat[0][3][tid];
            float qq = sstat[1][0][tid] + sstat[1][1][tid]
                     + sstat[1][2][tid] + sstat[1][3][tid];
            atomicAdd(&g_stats[stats_off + half * 64 + tid], s);
            atomicAdd(&g_stats[stats_off + HID + half * 64 + tid], qq);
        }
        __syncthreads();
    }
}

// ---------------- layer-3 GEMM: z' = gat16 @ W3' (NC=64, B staged in smem) ---
__global__ void __launch_bounds__(256) gemm3_kernel() {
    __shared__ __align__(16) unsigned char sraw[128 * 64 * 4]; // 32KB: sB then sC
    __half* sB = (__half*)sraw;
    float* sC = (float*)sraw;

    int tid = threadIdx.x;
    int w = tid >> 5;
    int row0 = blockIdx.x * 128;
    size_t arow = (size_t)(row0 + w * 16);

    #pragma unroll
    for (int l = tid; l < HID * OUTF / 8; l += 256)
        *(uint4*)(sB + l * 8) = *(const uint4*)(g_w3p + (size_t)l * 8);
    __syncthreads();

    wmma::fragment<wmma::accumulator, 16, 16, 16, float> acc[4];
    #pragma unroll
    for (int n = 0; n < 4; n++) wmma::fill_fragment(acc[n], 0.f);

    #pragma unroll
    for (int k = 0; k < 8; k++) {
        wmma::fragment<wmma::matrix_a, 16, 16, 16, __half, wmma::row_major> af;
        wmma::load_matrix_sync(af, g_gat16 + arow * HID + k * 16, HID);
        #pragma unroll
        for (int n = 0; n < 4; n++) {
            wmma::fragment<wmma::matrix_b, 16, 16, 16, __half, wmma::row_major> bf;
            wmma::load_matrix_sync(bf, sB + k * 16 * OUTF + n * 16, OUTF);
            wmma::mma_sync(acc[n], af, bf, acc[n]);
        }
    }
    __syncthreads();

    #pragma unroll
    for (int n = 0; n < 4; n++)
        wmma::store_matrix_sync(sC + w * 16 * 64 + n * 16, acc[n],
                                64, wmma::mem_row_major);
    __syncthreads();

    int col = tid & 63;
    int q = tid >> 6;
    #pragma unroll 4
    for (int r = q * 32; r < q * 32 + 32; r++) {
        int grow = row0 + r;
        if (grow < NN)
            g_z16[(size_t)grow * OUTF + col] = __float2half_rn(sC[r * 64 + col]);
    }
}

// ---------------- SpMM 64-wide + c3*sumns + bias + log_softmax --------------
__global__ void __launch_bounds__(256) spmm64_kernel(const float* __restrict__ b3,
                                                     float* __restrict__ out) {
    int t = blockIdx.x * 256 + threadIdx.x;
    int d = t >> 5;
    int lane = t & 31;
    if (d >= NN) return;
    int c = lane * 2;
    const __half* __restrict__ zbase = g_z16 + c;
    int beg = g_rowptr[d], end = g_rowptr[d + 1];
    float a0 = 0.f, a1 = 0.f;
    int j = beg;
    for (; j + 3 < end; j += 4) {
        int s0 = g_col[j], s1 = g_col[j + 1], s2 = g_col[j + 2], s3 = g_col[j + 3];
        __half2 v0 = *(const __half2*)(zbase + (size_t)s0 * OUTF);
        __half2 v1 = *(const __half2*)(zbase + (size_t)s1 * OUTF);
        __half2 v2 = *(const __half2*)(zbase + (size_t)s2 * OUTF);
        __half2 v3 = *(const __half2*)(zbase + (size_t)s3 * OUTF);
        float2 f01 = __half22float2(__hadd2(v0, v1));
        float2 f23 = __half22float2(__hadd2(v2, v3));
        a0 += f01.x + f23.x;
        a1 += f01.y + f23.y;
    }
    for (; j < end; j++) {
        int s = g_col[j];
        float2 v = __half22float2(*(const __half2*)(zbase + (size_t)s * OUTF));
        a0 += v.x; a1 += v.y;
    }
    float nd = g_normd[d];
    float sn = g_sumns[d];
    a0 = (a0 + g_c3[c] * sn) * nd + b3[c];
    a1 = (a1 + g_c3[c + 1] * sn) * nd + b3[c + 1];
    float mx = fmaxf(a0, a1);
    #pragma unroll
    for (int off = 16; off > 0; off >>= 1)
        mx = fmaxf(mx, __shfl_xor_sync(0xffffffffu, mx, off));
    float e = expf(a0 - mx) + expf(a1 - mx);
    #pragma unroll
    for (int off = 16; off > 0; off >>= 1)
        e += __shfl_xor_sync(0xffffffffu, e, off);
    float l = logf(e);
    out[(size_t)d * OUTF + c]     = a0 - mx - l;
    out[(size_t)d * OUTF + c + 1] = a1 - mx - l;
}

// ---------------- BN1 finalize ----------------
__global__ void bnfin1_kernel(const float* __restrict__ gamma, const float* __restrict__ beta) {
    int c = threadIdx.x;
    if (c < HID) {
        float inv_n = 1.0f / (float)NN;
        float mean = g_stats[c] * inv_n;
        float var = g_stats[HID + c] * inv_n - mean * mean;
        float sc = gamma[c] * rsqrtf(var + 1e-5f);
        g_scale1[c] = sc;
        g_shift1[c] = beta[c] - mean * sc;
    }
}

// ---------------- BN2 finalize + W3' + c3 ----------------
__global__ void finalize2_kernel(const float* __restrict__ gamma, const float* __restrict__ beta,
                                 const float* __restrict__ W3) {
    __shared__ float ssh[HID];
    int t = threadIdx.x;
    float inv_n = 1.0f / (float)NN;
    float mean = g_stats[256 + t] * inv_n;
    float var = g_stats[256 + HID + t] * inv_n - mean * mean;
    float sc = gamma[t] * rsqrtf(var + 1e-5f);
    float sh = beta[t] - mean * sc;
    ssh[t] = sh;
    __syncthreads();
    #pragma unroll 4
    for (int n = 0; n < OUTF; n++)
        g_w3p[t * OUTF + n] = __float2half_rn(sc * W3[t * OUTF + n]);
    if (t < OUTF) {
        float cc = 0.f;
        #pragma unroll 4
        for (int k = 0; k < HID; k++)
            cc += ssh[k] * W3[k * OUTF + t];
        g_c3[t] = cc;
    }
}

// ---------------- launch ----------------
extern "C" void kernel_launch(void* const* d_in, const int* in_sizes, int n_in,
                              void* d_out, int out_size) {
    const float* x      = (const float*)d_in[0];
    const void*  src    = d_in[1];
    const void*  dst    = d_in[2];
    const float* W1     = (const float*)d_in[3];
    const float* b1     = (const float*)d_in[4];
    const float* W2     = (const float*)d_in[5];
    const float* b2     = (const float*)d_in[6];
    const float* W3     = (const float*)d_in[7];
    const float* b3     = (const float*)d_in[8];
    const float* gamma1 = (const float*)d_in[9];
    const float* beta1  = (const float*)d_in[10];
    const float* gamma2 = (const float*)d_in[11];
    const float* beta2  = (const float*)d_in[12];
    float* out = (float*)d_out;

    const int NB  = (NN + 255) / 256;       // 391
    const int EB2 = (NE / 2 + 255) / 256;   // 6250
    const int GB  = (NN + 127) / 128;       // 782

    init_kernel<<<NB, 256>>>(src, W1, W2);
    degree_kernel<<<EB2, 256>>>(src, dst);
    scan_kernel<<<SCAN_NB, 256>>>();
    fillprep_kernel<<<EBF + WB, 256>>>(x);

    // layer 1: fused spmm+gemm (gat16 -> agg16), also produces sumns
    spgemm_kernel<0><<<GB, 256>>>(b1);
    bnfin1_kernel<<<1, 128>>>(gamma1, beta1);

    // layer 2: fused spmm+gemm (agg16 -> gat16), affine1 via sumns
    spgemm_kernel<1><<<GB, 256>>>(b2);
    finalize2_kernel<<<1, 128>>>(gamma2, beta2, W3);

    // layer 3
    gemm3_kernel<<<GB, 256>>>();
    spmm64_kernel<<<WB, 256>>>(b3, out);
}

// round 15
// speedup vs baseline: 1.1920x; 1.1920x over previous
#include <cuda_runtime.h>
#include <cuda_fp16.h>
#include <mma.h>
#include <cstdint>

using namespace nvcuda;

#define NN 100000
#define NNP 100096          // 782 * 128, padded for TC GEMM tiles
#define NE 3200000
#define HID 128
#define OUTF 64
#define SCAN_NB 391         // ceil(NN/256)
#define EBF 6250            // NE/(256*2) edge blocks, 2 edges/thread
#define WB 12500            // warp-per-node blocks

// ---------------- device scratch (static, no allocation) ----------------
// Symbols referenced ONLY inside device code (never passed from host).
__device__ int    g_degout[NN];
__device__ int    g_degin[NN];
__device__ float  g_stats[512];
__device__ unsigned long long g_scanstate[SCAN_NB];

__device__ int    g_is64;
__device__ float  g_norms[NN];
__device__ float  g_normd[NN];
__device__ float  g_sumns[NN];                // written by spmm128<false>
__device__ int    g_rowptr[NN + 1];
__device__ int    g_srci[NE];
__device__ unsigned g_dstr[NE];               // dst | (rank << 17)
__device__ int    g_col[NE];
// Buffer flow (R12): fillprep: gat16 = x*ns
//   spmm<false>: gat16 -> agg16 ; gemm<0>: agg16 -> gat16 (v1)
//   spmm<true> : gat16 -> agg16 ; gemm<1>: agg16 -> gat16 (v2)
//   gemm<2>    : gat16 -> z16
__device__ __half g_gat16[(size_t)NNP * HID]; // pad rows 0
__device__ __half g_agg16[(size_t)NNP * HID]; // pad rows 0
__device__ __half g_z16[(size_t)NN * OUTF];
__device__ __half g_w1[HID * HID];
__device__ __half g_w2[HID * HID];
__device__ __half g_w3p[HID * OUTF];          // sc2 ⊙ W3
__device__ float  g_c3[OUTF];                 // sh2 @ W3
__device__ float  g_scale1[HID], g_shift1[HID];

// ---------------- init: zero accumulators + detect dtype + convert W1/W2 ----
__global__ void init_kernel(const void* src, const float* __restrict__ W1,
                            const float* __restrict__ W2) {
    int i = blockIdx.x * blockDim.x + threadIdx.x;   // 391*256 = 100096
    if (i < NN) { g_degout[i] = 0; g_degin[i] = 0; }
    if (i < 512) g_stats[i] = 0.f;
    if (i < SCAN_NB) g_scanstate[i] = 0ull;
    if (i < HID * HID) {
        g_w1[i] = __float2half_rn(W1[i]);
        g_w2[i] = __float2half_rn(W2[i]);
    }
    if (i == 0) {
        const long long* p = (const long long*)src;
        int ok = 1;
        #pragma unroll 1
        for (int k = 0; k < 128; k++) {
            long long v = p[k];
            if (v < 0 || v >= NN) { ok = 0; break; }
        }
        g_is64 = ok;
    }
}

// ---------------- degrees + int32 conversion + packed dst|rank --------------
__global__ void __launch_bounds__(256) degree_kernel(const void* src, const void* dst) {
    int p = blockIdx.x * blockDim.x + threadIdx.x;   // pair index
    int e = p * 2;
    if (e >= NE) return;
    int s0, s1, d0, d1;
    if (g_is64) {
        longlong2 a = ((const longlong2*)src)[p];
        longlong2 b = ((const longlong2*)dst)[p];
        s0 = (int)a.x; s1 = (int)a.y;
        d0 = (int)b.x; d1 = (int)b.y;
    } else {
        int2 a = ((const int2*)src)[p];
        int2 b = ((const int2*)dst)[p];
        s0 = a.x; s1 = a.y;
        d0 = b.x; d1 = b.y;
    }
    *(int2*)(g_srci + e) = make_int2(s0, s1);
    atomicAdd(&g_degout[s0], 1);
    atomicAdd(&g_degout[s1], 1);
    unsigned r0 = (unsigned)atomicAdd(&g_degin[d0], 1);
    unsigned r1 = (unsigned)atomicAdd(&g_degin[d1], 1);
    *(uint2*)(g_dstr + e) = make_uint2((unsigned)d0 | (r0 << 17),
                                       (unsigned)d1 | (r1 << 17));
}

// ---------------- single-pass scan (decoupled lookback) + norms -------------
__global__ void __launch_bounds__(256) scan_kernel() {
    int bid = blockIdx.x;
    int t = threadIdx.x;
    int lane = t & 31, wid = t >> 5;
    int i = bid * 256 + t;
    int v = (i < NN) ? g_degin[i] : 0;

    int x = v;
    #pragma unroll
    for (int off = 1; off < 32; off <<= 1) {
        int y = __shfl_up_sync(0xffffffffu, x, off);
        if (lane >= off) x += y;
    }
    __shared__ int wsum[8];
    if (lane == 31) wsum[wid] = x;
    __syncthreads();
    if (wid == 0 && lane < 8) {
        int w = wsum[lane];
        #pragma unroll
        for (int off = 1; off < 8; off <<= 1) {
            int y = __shfl_up_sync(0xffu, w, off);
            if (lane >= off) w += y;
        }
        wsum[lane] = w;
    }
    __syncthreads();
    int incl = x + (wid > 0 ? wsum[wid - 1] : 0);
    int bsum = wsum[7];

    __shared__ int s_excl;
    if (t == 0) {
        if (bid == 0) {
            atomicExch(&g_scanstate[0], (2ull << 32) | (unsigned long long)(unsigned)bsum);
            s_excl = 0;
        } else {
            atomicExch(&g_scanstate[bid], (1ull << 32) | (unsigned long long)(unsigned)bsum);
            long long running = 0;
            int j = bid - 1;
            while (true) {
                unsigned long long st = atomicAdd(&g_scanstate[j], 0ull);
                unsigned f = (unsigned)(st >> 32);
                if (f == 0u) continue;
                running += (long long)(unsigned)st;
                if (f == 2u) break;
                j--;
            }
            s_excl = (int)running;
            atomicExch(&g_scanstate[bid],
                       (2ull << 32) | (unsigned long long)(unsigned)(running + bsum));
        }
    }
    __syncthreads();
    int base = s_excl;
    if (i < NN) {
        int r = base + incl - v;
        g_rowptr[i] = r;
        int dout = g_degout[i]; if (dout < 1) dout = 1;
        int din = v; if (din < 1) din = 1;
        g_norms[i] = rsqrtf((float)dout);
        g_normd[i] = rsqrtf((float)din);
        if (i == NN - 1) g_rowptr[NN] = r + v;
    }
}

// ---------------- fused: atomic-free CSR fill (rank trick) + prepx ----------
__global__ void __launch_bounds__(256) fillprep_kernel(const float* __restrict__ x) {
    int b = blockIdx.x;
    if (b < EBF) {
        int p = b * 256 + threadIdx.x;
        int e = p * 2;
        int2 ss = *(const int2*)(g_srci + e);
        uint2 dr = *(const uint2*)(g_dstr + e);
        g_col[g_rowptr[dr.x & 0x1FFFF] + (dr.x >> 17)] = ss.x;
        g_col[g_rowptr[dr.y & 0x1FFFF] + (dr.y >> 17)] = ss.y;
    } else {
        int t = (b - EBF) * 256 + threadIdx.x;
        int node = t >> 5;
        if (node >= NN) return;
        int c = (t & 31) * 4;
        float ns = g_norms[node];
        float4 v = *(const float4*)(x + (size_t)node * HID + c);
        __half2 h0 = __floats2half2_rn(v.x * ns, v.y * ns);
        __half2 h1 = __floats2half2_rn(v.z * ns, v.w * ns);
        uint2 u;
        u.x = *(unsigned*)&h0;
        u.y = *(unsigned*)&h1;
        *(uint2*)(g_gat16 + (size_t)node * HID + c) = u;
    }
}

// ---------------- SpMM 128-wide: warp per dst node, fp16 pairwise gather ----
// Reads g_gat16, writes g_agg16, ALWAYS (gemm writes back into g_gat16).
// AFFINE=false (layer 1): m = S * nd; also computes sumns[d] (broadcast loads)
// AFFINE=true  (layer 2): m = (sc1 ⊙ S + sh1 * sumns[d]) * nd
template<bool AFFINE>
__global__ void __launch_bounds__(256) spmm128_kernel() {
    int t = blockIdx.x * 256 + threadIdx.x;
    int d = t >> 5;
    int lane = t & 31;
    if (d >= NN) return;
    int c = lane * 4;
    const __half* __restrict__ gbase = g_gat16 + c;
    int beg = g_rowptr[d], end = g_rowptr[d + 1];
    float ax = 0.f, ay = 0.f, az = 0.f, aw = 0.f;
    float ws = 0.f;
    int j = beg;
    for (; j + 3 < end; j += 4) {
        int s0 = g_col[j], s1 = g_col[j + 1], s2 = g_col[j + 2], s3 = g_col[j + 3];
        uint2 u0 = *(const uint2*)(gbase + (size_t)s0 * HID);
        uint2 u1 = *(const uint2*)(gbase + (size_t)s1 * HID);
        uint2 u2 = *(const uint2*)(gbase + (size_t)s2 * HID);
        uint2 u3 = *(const uint2*)(gbase + (size_t)s3 * HID);
        if (!AFFINE)
            ws += (g_norms[s0] + g_norms[s1]) + (g_norms[s2] + g_norms[s3]);
        __half2 p0 = __hadd2(*(__half2*)&u0.x, *(__half2*)&u1.x);
        __half2 q0 = __hadd2(*(__half2*)&u2.x, *(__half2*)&u3.x);
        __half2 p1 = __hadd2(*(__half2*)&u0.y, *(__half2*)&u1.y);
        __half2 q1 = __hadd2(*(__half2*)&u2.y, *(__half2*)&u3.y);
        float2 f;
        f = __half22float2(p0); ax += f.x; ay += f.y;
        f = __half22float2(q0); ax += f.x; ay += f.y;
        f = __half22float2(p1); az += f.x; aw += f.y;
        f = __half22float2(q1); az += f.x; aw += f.y;
    }
    for (; j < end; j++) {
        int s = g_col[j];
        uint2 u = *(const uint2*)(gbase + (size_t)s * HID);
        if (!AFFINE) ws += g_norms[s];
        float2 a = __half22float2(*(__half2*)&u.x), b = __half22float2(*(__half2*)&u.y);
        ax += a.x; ay += a.y; az += b.x; aw += b.y;
    }
    float nd = g_normd[d];
    if (AFFINE) {
        float4 sc = *(const float4*)(g_scale1 + c);
        float4 sh = *(const float4*)(g_shift1 + c);
        float sn = g_sumns[d];
        ax = fmaf(sh.x, sn, ax * sc.x);
        ay = fmaf(sh.y, sn, ay * sc.y);
        az = fmaf(sh.z, sn, az * sc.z);
        aw = fmaf(sh.w, sn, aw * sc.w);
    } else {
        if (lane == 0) g_sumns[d] = ws;   // all lanes hold identical ws
    }
    __half2 h0 = __floats2half2_rn(ax * nd, ay * nd);
    __half2 h1 = __floats2half2_rn(az * nd, aw * nd);
    uint2 o;
    o.x = *(unsigned*)&h0;
    o.y = *(unsigned*)&h1;
    *(uint2*)(g_agg16 + (size_t)d * HID + c) = o;
}

// ---------------- Tensor-core GEMM (HMMA via wmma), B staged in smem --------
// L=0: v1 = relu(agg16 @ W1 + b1)*ns -> gat16; stats@0
// L=1: v2 = relu(agg16 @ W2 + b2)*ns -> gat16; stats@256
// L=2: z' = gat16 @ W3'              -> z16
template<int L>
__global__ void __launch_bounds__(256)
gemmtc_kernel(const float* __restrict__ bias) {
    constexpr bool STATS = (L < 2);
    constexpr int NC = STATS ? HID : OUTF;
    constexpr int NF = NC / 16;
    const __half* __restrict__ A = STATS ? g_agg16 : g_gat16;
    const __half* __restrict__ W = (L == 0) ? g_w1 : (L == 1) ? g_w2 : g_w3p;
    __half* __restrict__ C = STATS ? g_gat16 : g_z16;
    const int stats_off = (L == 1) ? 256 : 0;

    __shared__ __align__(16) unsigned char sraw[128 * 64 * 4]; // 32KB: sB then sC
    __shared__ float sstat[2][4][64];
    __half* sB = (__half*)sraw;
    float* sC = (float*)sraw;

    int tid = threadIdx.x;
    int w = tid >> 5;
    int row0 = blockIdx.x * 128;
    size_t arow = (size_t)(row0 + w * 16);

    constexpr int NB16 = HID * NC / 8;
    #pragma unroll
    for (int l = tid; l < NB16; l += 256)
        *(uint4*)(sB + l * 8) = *(const uint4*)(W + (size_t)l * 8);
    __syncthreads();

    wmma::fragment<wmma::accumulator, 16, 16, 16, float> acc[NF];
    #pragma unroll
    for (int n = 0; n < NF; n++) wmma::fill_fragment(acc[n], 0.f);

    #pragma unroll
    for (int k = 0; k < 8; k++) {
        wmma::fragment<wmma::matrix_a, 16, 16, 16, __half, wmma::row_major> af;
        wmma::load_matrix_sync(af, A + arow * HID + k * 16, HID);
        #pragma unroll
        for (int n = 0; n < NF; n++) {
            wmma::fragment<wmma::matrix_b, 16, 16, 16, __half, wmma::row_major> bf;
            wmma::load_matrix_sync(bf, sB + k * 16 * NC + n * 16, NC);
            wmma::mma_sync(acc[n], af, bf, acc[n]);
        }
    }
    __syncthreads();   // done with sB; sC reuses the space

    #pragma unroll
    for (int half = 0; half < NC / 64; half++) {
        #pragma unroll
        for (int n = 0; n < 4; n++)
            wmma::store_matrix_sync(sC + w * 16 * 64 + n * 16, acc[half * 4 + n],
                                    64, wmma::mem_row_major);
        __syncthreads();

        int col = tid & 63;
        int q = tid >> 6;
        int gcol = half * 64 + col;
        float bb = STATS ? bias[gcol] : 0.f;
        float ps = 0.f, pq = 0.f;
        #pragma unroll 4
        for (int r = q * 32; r < q * 32 + 32; r++) {
            int grow = row0 + r;
            if (grow < NN) {
                float v = sC[r * 64 + col];
                if (STATS) {
                    v += bb;
                    v = fmaxf(v, 0.f);
                    ps += v;
                    pq += v * v;
                    v *= g_norms[grow];   // fold norm_s into stored operand
                }
                C[(size_t)grow * NC + gcol] = __float2half_rn(v);
            }
        }
        if (STATS) {
            sstat[0][q][col] = ps;
            sstat[1][q][col] = pq;
            __syncthreads();
            if (tid < 64) {
                float s = sstat[0][0][tid] + sstat[0][1][tid]
                        + sstat[0][2][tid] + sstat[0][3][tid];
                float qq = sstat[1][0][tid] + sstat[1][1][tid]
                         + sstat[1][2][tid] + sstat[1][3][tid];
                atomicAdd(&g_stats[stats_off + half * 64 + tid], s);
                atomicAdd(&g_stats[stats_off + NC + half * 64 + tid], qq);
            }
        }
        __syncthreads();
    }
}

// ---------------- SpMM 64-wide + c3*sumns + bias + log_softmax --------------
__global__ void __launch_bounds__(256) spmm64_kernel(const float* __restrict__ b3,
                                                     float* __restrict__ out) {
    int t = blockIdx.x * 256 + threadIdx.x;
    int d = t >> 5;
    int lane = t & 31;
    if (d >= NN) return;
    int c = lane * 2;
    const __half* __restrict__ zbase = g_z16 + c;
    int beg = g_rowptr[d], end = g_rowptr[d + 1];
    float a0 = 0.f, a1 = 0.f;
    int j = beg;
    for (; j + 3 < end; j += 4) {
        int s0 = g_col[j], s1 = g_col[j + 1], s2 = g_col[j + 2], s3 = g_col[j + 3];
        __half2 v0 = *(const __half2*)(zbase + (size_t)s0 * OUTF);
        __half2 v1 = *(const __half2*)(zbase + (size_t)s1 * OUTF);
        __half2 v2 = *(const __half2*)(zbase + (size_t)s2 * OUTF);
        __half2 v3 = *(const __half2*)(zbase + (size_t)s3 * OUTF);
        float2 f01 = __half22float2(__hadd2(v0, v1));
        float2 f23 = __half22float2(__hadd2(v2, v3));
        a0 += f01.x + f23.x;
        a1 += f01.y + f23.y;
    }
    for (; j < end; j++) {
        int s = g_col[j];
        float2 v = __half22float2(*(const __half2*)(zbase + (size_t)s * OUTF));
        a0 += v.x; a1 += v.y;
    }
    float nd = g_normd[d];
    float sn = g_sumns[d];
    a0 = (a0 + g_c3[c] * sn) * nd + b3[c];
    a1 = (a1 + g_c3[c + 1] * sn) * nd + b3[c + 1];
    float mx = fmaxf(a0, a1);
    #pragma unroll
    for (int off = 16; off > 0; off >>= 1)
        mx = fmaxf(mx, __shfl_xor_sync(0xffffffffu, mx, off));
    float e = expf(a0 - mx) + expf(a1 - mx);
    #pragma unroll
    for (int off = 16; off > 0; off >>= 1)
        e += __shfl_xor_sync(0xffffffffu, e, off);
    float l = logf(e);
    out[(size_t)d * OUTF + c]     = a0 - mx - l;
    out[(size_t)d * OUTF + c + 1] = a1 - mx - l;
}

// ---------------- BN1 finalize ----------------
__global__ void bnfin1_kernel(const float* __restrict__ gamma, const float* __restrict__ beta) {
    int c = threadIdx.x;
    if (c < HID) {
        float inv_n = 1.0f / (float)NN;
        float mean = g_stats[c] * inv_n;
        float var = g_stats[HID + c] * inv_n - mean * mean;
        float sc = gamma[c] * rsqrtf(var + 1e-5f);
        g_scale1[c] = sc;
        g_shift1[c] = beta[c] - mean * sc;
    }
}

// ---------------- BN2 finalize + W3' + c3 ----------------
__global__ void finalize2_kernel(const float* __restrict__ gamma, const float* __restrict__ beta,
                                 const float* __restrict__ W3) {
    __shared__ float ssh[HID];
    int t = threadIdx.x;
    float inv_n = 1.0f / (float)NN;
    float mean = g_stats[256 + t] * inv_n;
    float var = g_stats[256 + HID + t] * inv_n - mean * mean;
    float sc = gamma[t] * rsqrtf(var + 1e-5f);
    float sh = beta[t] - mean * sc;
    ssh[t] = sh;
    __syncthreads();
    #pragma unroll 4
    for (int n = 0; n < OUTF; n++)
        g_w3p[t * OUTF + n] = __float2half_rn(sc * W3[t * OUTF + n]);
    if (t < OUTF) {
        float cc = 0.f;
        #pragma unroll 4
        for (int k = 0; k < HID; k++)
            cc += ssh[k] * W3[k * OUTF + t];
        g_c3[t] = cc;
    }
}

// ---------------- launch ----------------
extern "C" void kernel_launch(void* const* d_in, const int* in_sizes, int n_in,
                              void* d_out, int out_size) {
    const float* x      = (const float*)d_in[0];
    const void*  src    = d_in[1];
    const void*  dst    = d_in[2];
    const float* W1     = (const float*)d_in[3];
    const float* b1     = (const float*)d_in[4];
    const float* W2     = (const float*)d_in[5];
    const float* b2     = (const float*)d_in[6];
    const float* W3     = (const float*)d_in[7];
    const float* b3     = (const float*)d_in[8];
    const float* gamma1 = (const float*)d_in[9];
    const float* beta1  = (const float*)d_in[10];
    const float* gamma2 = (const float*)d_in[11];
    const float* beta2  = (const float*)d_in[12];
    float* out = (float*)d_out;

    const int NB  = (NN + 255) / 256;       // 391
    const int EB2 = (NE / 2 + 255) / 256;   // 6250
    const int GB  = (NN + 127) / 128;       // 782

    init_kernel<<<NB, 256>>>(src, W1, W2);
    degree_kernel<<<EB2, 256>>>(src, dst);
    scan_kernel<<<SCAN_NB, 256>>>();
    fillprep_kernel<<<EBF + WB, 256>>>(x);

    // layer 1: spmm gat16->agg16 (also produces sumns), gemm agg16->gat16 (v1)
    spmm128_kernel<false><<<WB, 256>>>();
    gemmtc_kernel<0><<<GB, 256>>>(b1);
    bnfin1_kernel<<<1, 128>>>(gamma1, beta1);

    // layer 2: spmm gat16(v1)->agg16 (affine1 via sumns), gemm agg16->gat16 (v2)
    spmm128_kernel<true><<<WB, 256>>>();
    gemmtc_kernel<1><<<GB, 256>>>(b2);
    finalize2_kernel<<<1, 128>>>(gamma2, beta2, W3);

    // layer 3: gemm gat16(v2)->z16, spmm64 + softmax
    gemmtc_kernel<2><<<GB, 256>>>(nullptr);
    spmm64_kernel<<<WB, 256>>>(b3, out);
}